// round 9
// baseline (speedup 1.0000x reference)
#include <cuda_runtime.h>
#include <cstdint>

#define S_DIM 4
#define N_DIM 4096
#define D_DIM 64
#define NSM   148
#define NTILE (S_DIM * (N_DIM / 128) * (N_DIM / 128))   // 4096

// Split-bf16 scratch, pair-packed along k: word = (bf16 2p | bf16 2p+1 << 16)
#define PAIR_WORDS (S_DIM * N_DIM * D_DIM / 2)
__device__ uint32_t g_Xh[PAIR_WORDS];
__device__ uint32_t g_Xl[PAIR_WORDS];
__device__ uint32_t g_Qh[PAIR_WORDS];
__device__ uint32_t g_Ql[PAIR_WORDS];

__device__ __forceinline__ uint32_t smem_u32(const void* p) {
    uint32_t a;
    asm("{ .reg .u64 t; cvta.to.shared.u64 t, %1; cvt.u32.u64 %0, t; }"
        : "=r"(a) : "l"(p));
    return a;
}
__device__ __forceinline__ uint32_t bf16x2(float a, float b) {
    uint32_t d;
    asm("cvt.rn.bf16x2.f32 %0, %1, %2;" : "=r"(d) : "f"(b), "f"(a));
    return d;
}
__device__ __forceinline__ void split2(float a, float b, uint32_t& hw, uint32_t& lw) {
    hw = bf16x2(a, b);
    float ha = __uint_as_float(hw << 16);
    float hb = __uint_as_float(hw & 0xFFFF0000u);
    lw = bf16x2(a - ha, b - hb);
}
__device__ __forceinline__ void mma_bf16(float d[4], const uint32_t a[4], const uint32_t b[2]) {
    asm volatile(
        "mma.sync.aligned.m16n8k16.row.col.f32.bf16.bf16.f32 "
        "{%0,%1,%2,%3}, {%4,%5,%6,%7}, {%8,%9}, {%0,%1,%2,%3};"
        : "+f"(d[0]), "+f"(d[1]), "+f"(d[2]), "+f"(d[3])
        : "r"(a[0]), "r"(a[1]), "r"(a[2]), "r"(a[3]), "r"(b[0]), "r"(b[1]));
}
__device__ __forceinline__ void ldsm_x4(uint32_t r[4], uint32_t addr) {
    asm volatile("ldmatrix.sync.aligned.m8n8.x4.shared.b16 {%0,%1,%2,%3}, [%4];"
                 : "=r"(r[0]), "=r"(r[1]), "=r"(r[2]), "=r"(r[3]) : "r"(addr));
}
__device__ __forceinline__ void ldsm_x2(uint32_t r[2], uint32_t addr) {
    asm volatile("ldmatrix.sync.aligned.m8n8.x2.shared.b16 {%0,%1}, [%2];"
                 : "=r"(r[0]), "=r"(r[1]) : "r"(addr));
}

// ---------------------------------------------------------------------------
// Fused prep: blocks [0,256) compute Q + split; blocks [256,1280) split x1.
// ---------------------------------------------------------------------------
__device__ __forceinline__ void load_tile_transposed64(
    const float* __restrict__ gsrc, float* sdst, int t)
{
    const float4* g4 = reinterpret_cast<const float4*>(gsrc);
#pragma unroll
    for (int p = 0; p < 4; ++p) {
        int f4 = p * 256 + t;
        int x  = f4 >> 4;
        int k4 = (f4 & 15) << 2;
        float4 v = g4[f4];
        float vv[4] = {v.x, v.y, v.z, v.w};
#pragma unroll
        for (int q = 0; q < 4; ++q) {
            int k  = k4 + q;
            int c4 = (x >> 2) ^ ((k >> 2) & 15);
            sdst[k * 64 + c4 * 4 + (x & 3)] = vv[q];
        }
    }
}

__global__ __launch_bounds__(256) void prep_kernel(
    const float* __restrict__ x0, const float* __restrict__ x1,
    const float* __restrict__ W)
{
    __shared__ float Xs[64 * 64];
    __shared__ float Ws[64 * 64];
    int t = threadIdx.x;

    if (blockIdx.x >= 256) {
        int i = (blockIdx.x - 256) * 256 + t;
        float4 v = reinterpret_cast<const float4*>(x1)[i];
        uint2 h, l;
        split2(v.x, v.y, h.x, l.x);
        split2(v.z, v.w, h.y, l.y);
        reinterpret_cast<uint2*>(g_Xh)[i] = h;
        reinterpret_cast<uint2*>(g_Xl)[i] = l;
        return;
    }

    int r0 = blockIdx.x * 64;
    load_tile_transposed64(x0 + (size_t)r0 * 64, Xs, t);
    load_tile_transposed64(W, Ws, t);
    __syncthreads();

    int tx = t & 15, ty = t >> 4;
    float acc[4][4] = {};
#pragma unroll
    for (int k = 0; k < 64; ++k) {
        int sw = (k >> 2) & 15;
        float4 a = *reinterpret_cast<const float4*>(&Xs[k * 64 + ((ty ^ sw) << 2)]);
        float4 b = *reinterpret_cast<const float4*>(&Ws[k * 64 + ((tx ^ sw) << 2)]);
        float av[4] = {a.x, a.y, a.z, a.w};
        float bv[4] = {b.x, b.y, b.z, b.w};
#pragma unroll
        for (int ra = 0; ra < 4; ++ra)
#pragma unroll
            for (int rb = 0; rb < 4; ++rb)
                acc[ra][rb] += av[ra] * bv[rb];
    }

#pragma unroll
    for (int ra = 0; ra < 4; ++ra) {
        int r = r0 + ty * 4 + ra;
        uint2 h, l;
        split2(acc[ra][0], acc[ra][1], h.x, l.x);
        split2(acc[ra][2], acc[ra][3], h.y, l.y);
        int p0 = r * 32 + 2 * tx;
        *reinterpret_cast<uint2*>(&g_Qh[p0]) = h;
        *reinterpret_cast<uint2*>(&g_Ql[p0]) = l;
    }
}

// ---------------------------------------------------------------------------
// Stage 2: persistent double-buffered 3-pass split-bf16 GEMM.
// Grid = 148 CTAs (1/SM), 512 threads = 16 warps (4m x 4n), warp tile 32x32.
// Each CTA streams ~28 tiles of 128x128: mainloop(buf) -> prefetch(buf^1)
// -> store epilogue, so operand loads + stores + MMA all interleave.
// Smem: 2 x 4 tiles [128][36 pair-words] = 147 KB.
// ---------------------------------------------------------------------------
#define PADW 36
#define TILE_W (128 * PADW)
#define BUF_W  (4 * TILE_W)
#define SMEM_DYN (2 * BUF_W * 4)
#define A_MT_BYTES (16 * PADW * 4)
#define B_NT_BYTES (8 * PADW * 4)
#define KT_BYTES   32

// 512-thread fill of one [128][32]-pair tile (1024 16B chunks)
__device__ __forceinline__ void fill_tile_async(
    const uint32_t* __restrict__ gsrc, uint32_t* sdst, int t)
{
#pragma unroll
    for (int it = 0; it < 2; ++it) {
        int f4 = it * 512 + t;
        int r  = f4 >> 3;
        int c4 = f4 & 7;
        uint32_t sa = smem_u32(&sdst[r * PADW + c4 * 4]);
        asm volatile("cp.async.cg.shared.global [%0], [%1], 16;"
                     :: "r"(sa), "l"(gsrc + f4 * 4) : "memory");
    }
}

__device__ __forceinline__ void fill_buf(uint32_t* buf, int tile, int t)
{
    int s   = tile >> 10;
    int rem = tile & 1023;
    int i0  = (rem >> 5) << 7;
    int j0  = (rem & 31) << 7;
    size_t abase = (size_t)(s * N_DIM + i0) * (D_DIM / 2);
    size_t bbase = (size_t)(s * N_DIM + j0) * (D_DIM / 2);
    fill_tile_async(g_Xh + abase, buf, t);
    fill_tile_async(g_Xl + abase, buf + TILE_W, t);
    fill_tile_async(g_Qh + bbase, buf + 2 * TILE_W, t);
    fill_tile_async(g_Ql + bbase, buf + 3 * TILE_W, t);
    asm volatile("cp.async.commit_group;" ::: "memory");
}

__global__ __launch_bounds__(512, 1) void bilinear_mma_kernel(
    const float* __restrict__ bias, float* __restrict__ out)
{
    extern __shared__ uint32_t sm[];

    int t    = threadIdx.x;
    int warp = t >> 5;
    int lane = t & 31;
    int wm   = warp >> 2;      // 0..3  (m, 32 rows each)
    int wn   = warp & 3;       // 0..3  (n, 32 cols each)
    int g    = lane >> 2;      // 0..7
    int tg   = lane & 3;       // 0..3

    // ldmatrix per-lane addressing (same geometry as round 8)
    int rowA   = (lane & 7) + 8 * ((lane >> 3) & 1);
    int kplusA = (lane >> 4) & 1;
    int rowB   = lane & 7;
    int kplusB = (lane >> 3) & 1;

    float bv = __ldg(bias);
    const size_t batch_stride = (size_t)S_DIM * N_DIM * N_DIM;

    int tile = blockIdx.x;
    if (tile >= NTILE) return;

    int cur = 0;
    fill_buf(sm, tile, t);

    while (true) {
        uint32_t* buf = sm + cur * BUF_W;

        asm volatile("cp.async.wait_group 0;" ::: "memory");
        __syncthreads();

        uint32_t aAh = smem_u32(buf) + ((wm * 32 + rowA) * PADW + kplusA * 4) * 4;
        uint32_t aAl = aAh + TILE_W * 4;
        uint32_t aBh = smem_u32(buf + 2 * TILE_W) + ((wn * 32 + rowB) * PADW + kplusB * 4) * 4;
        uint32_t aBl = aBh + TILE_W * 4;

        float acc[2][4][4];
#pragma unroll
        for (int a = 0; a < 2; ++a)
#pragma unroll
            for (int b = 0; b < 4; ++b)
#pragma unroll
                for (int c = 0; c < 4; ++c) acc[a][b][c] = 0.0f;

#pragma unroll
        for (int kt = 0; kt < 4; ++kt) {
            uint32_t ah[2][4], al[2][4];
            uint32_t bh[4][2], bl[4][2];
#pragma unroll
            for (int mt = 0; mt < 2; ++mt) {
                ldsm_x4(ah[mt], aAh + mt * A_MT_BYTES + kt * KT_BYTES);
                ldsm_x4(al[mt], aAl + mt * A_MT_BYTES + kt * KT_BYTES);
            }
#pragma unroll
            for (int nt = 0; nt < 4; ++nt) {
                ldsm_x2(bh[nt], aBh + nt * B_NT_BYTES + kt * KT_BYTES);
                ldsm_x2(bl[nt], aBl + nt * B_NT_BYTES + kt * KT_BYTES);
            }
#pragma unroll
            for (int mt = 0; mt < 2; ++mt)
#pragma unroll
                for (int nt = 0; nt < 4; ++nt)
                    mma_bf16(acc[mt][nt], ah[mt], bh[nt]);   // hi*hi
#pragma unroll
            for (int mt = 0; mt < 2; ++mt)
#pragma unroll
                for (int nt = 0; nt < 4; ++nt)
                    mma_bf16(acc[mt][nt], al[mt], bh[nt]);   // lo*hi
#pragma unroll
            for (int mt = 0; mt < 2; ++mt)
#pragma unroll
                for (int nt = 0; nt < 4; ++nt)
                    mma_bf16(acc[mt][nt], ah[mt], bl[nt]);   // hi*lo
        }

        __syncthreads();   // all warps done reading buf before refilling peer use

        int next = tile + NSM;
        if (next < NTILE) fill_buf(sm + (cur ^ 1) * BUF_W, next, t);

        // Epilogue: store this tile's 128x128 block (both batch copies)
        int s   = tile >> 10;
        int rem = tile & 1023;
        int i0  = (rem >> 5) << 7;
        int j0  = (rem & 31) << 7;
#pragma unroll
        for (int mt = 0; mt < 2; ++mt) {
#pragma unroll
            for (int h = 0; h < 2; ++h) {
                int i = i0 + wm * 32 + mt * 16 + g + 8 * h;
                size_t rowoff = ((size_t)s * N_DIM + i) * N_DIM;
#pragma unroll
                for (int nt = 0; nt < 4; ++nt) {
                    int j = j0 + wn * 32 + nt * 8 + 2 * tg;
                    float2 v;
                    v.x = acc[mt][nt][2 * h + 0] + bv;
                    v.y = acc[mt][nt][2 * h + 1] + bv;
                    __stcs(reinterpret_cast<float2*>(&out[rowoff + j]), v);
                    __stcs(reinterpret_cast<float2*>(&out[rowoff + j + batch_stride]), v);
                }
            }
        }

        if (next >= NTILE) break;
        tile = next;
        cur ^= 1;
    }
}

extern "C" void kernel_launch(void* const* d_in, const int* in_sizes, int n_in,
                              void* d_out, int out_size)
{
    const float* x0   = (const float*)d_in[0];  // tensor0 (S,N,D)
    const float* x1   = (const float*)d_in[1];  // tensor1 (S,N,D)
    const float* W    = (const float*)d_in[2];  // kernel  (D,D)
    const float* bias = (const float*)d_in[3];  // scalar
    float* out = (float*)d_out;                 // (2,S,N,N)

    cudaFuncSetAttribute(bilinear_mma_kernel,
                         cudaFuncAttributeMaxDynamicSharedMemorySize, SMEM_DYN);

    prep_kernel<<<256 + (S_DIM * N_DIM * D_DIM) / (256 * 4), 256>>>(x0, x1, W);

    bilinear_mma_kernel<<<NSM, 512, SMEM_DYN>>>(bias, out);
}

// round 10
// speedup vs baseline: 1.2410x; 1.2410x over previous
#include <cuda_runtime.h>
#include <cstdint>

#define S_DIM 4
#define N_DIM 4096
#define D_DIM 64
#define NTILE 4096          // 4 s * 32 i * 32 j
#define NCTA  296           // 2 per SM
#define CHUNK 14            // ceil(4096/296)

// Split-bf16 scratch, pair-packed along k: word = (bf16 2p | bf16 2p+1 << 16)
#define PAIR_WORDS (S_DIM * N_DIM * D_DIM / 2)
__device__ uint32_t g_Xh[PAIR_WORDS];
__device__ uint32_t g_Xl[PAIR_WORDS];
__device__ uint32_t g_Qh[PAIR_WORDS];
__device__ uint32_t g_Ql[PAIR_WORDS];

__device__ __forceinline__ uint32_t smem_u32(const void* p) {
    uint32_t a;
    asm("{ .reg .u64 t; cvta.to.shared.u64 t, %1; cvt.u32.u64 %0, t; }"
        : "=r"(a) : "l"(p));
    return a;
}
__device__ __forceinline__ uint32_t bf16x2(float a, float b) {
    uint32_t d;
    asm("cvt.rn.bf16x2.f32 %0, %1, %2;" : "=r"(d) : "f"(b), "f"(a));
    return d;
}
__device__ __forceinline__ void split2(float a, float b, uint32_t& hw, uint32_t& lw) {
    hw = bf16x2(a, b);
    float ha = __uint_as_float(hw << 16);
    float hb = __uint_as_float(hw & 0xFFFF0000u);
    lw = bf16x2(a - ha, b - hb);
}
__device__ __forceinline__ void mma_bf16(float d[4], const uint32_t a[4], const uint32_t b[2]) {
    asm volatile(
        "mma.sync.aligned.m16n8k16.row.col.f32.bf16.bf16.f32 "
        "{%0,%1,%2,%3}, {%4,%5,%6,%7}, {%8,%9}, {%0,%1,%2,%3};"
        : "+f"(d[0]), "+f"(d[1]), "+f"(d[2]), "+f"(d[3])
        : "r"(a[0]), "r"(a[1]), "r"(a[2]), "r"(a[3]), "r"(b[0]), "r"(b[1]));
}
__device__ __forceinline__ void ldsm_x4(uint32_t r[4], uint32_t addr) {
    asm volatile("ldmatrix.sync.aligned.m8n8.x4.shared.b16 {%0,%1,%2,%3}, [%4];"
                 : "=r"(r[0]), "=r"(r[1]), "=r"(r[2]), "=r"(r[3]) : "r"(addr));
}
__device__ __forceinline__ void ldsm_x2(uint32_t r[2], uint32_t addr) {
    asm volatile("ldmatrix.sync.aligned.m8n8.x2.shared.b16 {%0,%1}, [%2];"
                 : "=r"(r[0]), "=r"(r[1]) : "r"(addr));
}

// ---------------------------------------------------------------------------
// Fused prep: blocks [0,256) compute Q + split; blocks [256,1280) split x1.
// ---------------------------------------------------------------------------
__device__ __forceinline__ void load_tile_transposed64(
    const float* __restrict__ gsrc, float* sdst, int t)
{
    const float4* g4 = reinterpret_cast<const float4*>(gsrc);
#pragma unroll
    for (int p = 0; p < 4; ++p) {
        int f4 = p * 256 + t;
        int x  = f4 >> 4;
        int k4 = (f4 & 15) << 2;
        float4 v = g4[f4];
        float vv[4] = {v.x, v.y, v.z, v.w};
#pragma unroll
        for (int q = 0; q < 4; ++q) {
            int k  = k4 + q;
            int c4 = (x >> 2) ^ ((k >> 2) & 15);
            sdst[k * 64 + c4 * 4 + (x & 3)] = vv[q];
        }
    }
}

__global__ __launch_bounds__(256) void prep_kernel(
    const float* __restrict__ x0, const float* __restrict__ x1,
    const float* __restrict__ W)
{
    __shared__ float Xs[64 * 64];
    __shared__ float Ws[64 * 64];
    int t = threadIdx.x;

    if (blockIdx.x >= 256) {
        int i = (blockIdx.x - 256) * 256 + t;
        float4 v = reinterpret_cast<const float4*>(x1)[i];
        uint2 h, l;
        split2(v.x, v.y, h.x, l.x);
        split2(v.z, v.w, h.y, l.y);
        reinterpret_cast<uint2*>(g_Xh)[i] = h;
        reinterpret_cast<uint2*>(g_Xl)[i] = l;
        return;
    }

    int r0 = blockIdx.x * 64;
    load_tile_transposed64(x0 + (size_t)r0 * 64, Xs, t);
    load_tile_transposed64(W, Ws, t);
    __syncthreads();

    int tx = t & 15, ty = t >> 4;
    float acc[4][4] = {};
#pragma unroll
    for (int k = 0; k < 64; ++k) {
        int sw = (k >> 2) & 15;
        float4 a = *reinterpret_cast<const float4*>(&Xs[k * 64 + ((ty ^ sw) << 2)]);
        float4 b = *reinterpret_cast<const float4*>(&Ws[k * 64 + ((tx ^ sw) << 2)]);
        float av[4] = {a.x, a.y, a.z, a.w};
        float bv[4] = {b.x, b.y, b.z, b.w};
#pragma unroll
        for (int ra = 0; ra < 4; ++ra)
#pragma unroll
            for (int rb = 0; rb < 4; ++rb)
                acc[ra][rb] += av[ra] * bv[rb];
    }

#pragma unroll
    for (int ra = 0; ra < 4; ++ra) {
        int r = r0 + ty * 4 + ra;
        uint2 h, l;
        split2(acc[ra][0], acc[ra][1], h.x, l.x);
        split2(acc[ra][2], acc[ra][3], h.y, l.y);
        int p0 = r * 32 + 2 * tx;
        *reinterpret_cast<uint2*>(&g_Qh[p0]) = h;
        *reinterpret_cast<uint2*>(&g_Ql[p0]) = l;
    }
}

// ---------------------------------------------------------------------------
// Stage 2: persistent 3-pass split-bf16 GEMM, 296 CTAs (2/SM) x 256 threads.
// Each CTA walks ~14 consecutive j-fastest tiles: A resident across the band
// (refill on the rare i-boundary), B double-buffered (prefetch under mainloop).
// Mainloop/epilogue = round-8 geometry: 8 warps (2m x 4n), warp 64x32,
// kt-outer, 64 accumulators, pass-major MMA issue, ldmatrix fragments.
// Smem: A(hi,lo) + 2 x B(hi,lo) tiles [128][36 pair-words] = 110.6 KB.
// ---------------------------------------------------------------------------
#define PADW 36
#define TILE_W (128 * PADW)
#define SMEM_DYN (6 * TILE_W * 4)
#define A_MT_BYTES (16 * PADW * 4)
#define B_NT_BYTES (8 * PADW * 4)
#define KT_BYTES   32

// 256-thread fill of one [128][32]-pair array (1024 16B chunks)
__device__ __forceinline__ void fill_arr_async(
    const uint32_t* __restrict__ gsrc, uint32_t* sdst, int t)
{
#pragma unroll
    for (int it = 0; it < 4; ++it) {
        int f4 = it * 256 + t;
        int r  = f4 >> 3;
        int c4 = f4 & 7;
        uint32_t sa = smem_u32(&sdst[r * PADW + c4 * 4]);
        asm volatile("cp.async.cg.shared.global [%0], [%1], 16;"
                     :: "r"(sa), "l"(gsrc + f4 * 4) : "memory");
    }
}

__device__ __forceinline__ void fill_A(uint32_t* As, int s, int i0, int t) {
    size_t base = (size_t)(s * N_DIM + i0) * (D_DIM / 2);
    fill_arr_async(g_Xh + base, As, t);
    fill_arr_async(g_Xl + base, As + TILE_W, t);
}
__device__ __forceinline__ void fill_B(uint32_t* Bb, int s, int j0, int t) {
    size_t base = (size_t)(s * N_DIM + j0) * (D_DIM / 2);
    fill_arr_async(g_Qh + base, Bb, t);
    fill_arr_async(g_Ql + base, Bb + TILE_W, t);
}

__global__ __launch_bounds__(256, 2) void bilinear_mma_kernel(
    const float* __restrict__ bias, float* __restrict__ out)
{
    extern __shared__ uint32_t sm[];
    uint32_t* As = sm;                       // 2*TILE_W (hi, lo)
    uint32_t* Bbuf[2] = { sm + 2 * TILE_W, sm + 4 * TILE_W };

    int t    = threadIdx.x;
    int warp = t >> 5;
    int lane = t & 31;
    int wm   = warp >> 2;      // 0..1  (m, 64 rows)
    int wn   = warp & 3;       // 0..3  (n, 32 cols)
    int g    = lane >> 2;      // 0..7
    int tg   = lane & 3;       // 0..3

    // ldmatrix per-lane addressing
    int rowA   = (lane & 7) + 8 * ((lane >> 3) & 1);
    int kplusA = (lane >> 4) & 1;
    int rowB   = lane & 7;
    int kplusB = (lane >> 3) & 1;

    int start = blockIdx.x * CHUNK;
    if (start >= NTILE) return;
    int end = start + CHUNK;
    if (end > NTILE) end = NTILE;

    float bv = __ldg(bias);
    const size_t batch_stride = (size_t)S_DIM * N_DIM * N_DIM;

    // decode helpers: lt -> s = lt>>10, i0 = ((lt>>5)&31)<<7, j0 = (lt&31)<<7
    int s0 = start >> 10;
    int iB0 = (start >> 5) & 31;
    fill_A(As, s0, iB0 << 7, t);
    fill_B(Bbuf[0], s0, (start & 31) << 7, t);
    asm volatile("cp.async.commit_group;" ::: "memory");

    int cur   = 0;
    int cur_i = start >> 5;      // (s,i) band id

    uint32_t aAhBase = smem_u32(As) + ((wm * 64 + rowA) * PADW + kplusA * 4) * 4;

    for (int lt = start; lt < end; ++lt) {
        int s  = lt >> 10;
        int i0 = ((lt >> 5) & 31) << 7;
        int j0 = (lt & 31) << 7;

        asm volatile("cp.async.wait_group 0;" ::: "memory");
        __syncthreads();

        // A band change (<=1 per CTA): refill A, wait, resync
        if ((lt >> 5) != cur_i) {
            fill_A(As, s, i0, t);
            asm volatile("cp.async.commit_group;" ::: "memory");
            asm volatile("cp.async.wait_group 0;" ::: "memory");
            __syncthreads();
            cur_i = lt >> 5;
        }

        // Prefetch next B under this tile's compute
        int nxt = lt + 1;
        if (nxt < end) {
            fill_B(Bbuf[cur ^ 1], nxt >> 10, (nxt & 31) << 7, t);
            asm volatile("cp.async.commit_group;" ::: "memory");
        }

        uint32_t aAh = aAhBase;
        uint32_t aAl = aAh + TILE_W * 4;
        uint32_t aBh = smem_u32(Bbuf[cur]) + ((wn * 32 + rowB) * PADW + kplusB * 4) * 4;
        uint32_t aBl = aBh + TILE_W * 4;

        float acc[4][4][4];
#pragma unroll
        for (int a = 0; a < 4; ++a)
#pragma unroll
            for (int b = 0; b < 4; ++b)
#pragma unroll
                for (int c = 0; c < 4; ++c) acc[a][b][c] = 0.0f;

#pragma unroll
        for (int kt = 0; kt < 4; ++kt) {
            uint32_t ah[4][4], al[4][4];
            uint32_t bh[4][2], bl[4][2];
#pragma unroll
            for (int mt = 0; mt < 4; ++mt) {
                ldsm_x4(ah[mt], aAh + mt * A_MT_BYTES + kt * KT_BYTES);
                ldsm_x4(al[mt], aAl + mt * A_MT_BYTES + kt * KT_BYTES);
            }
#pragma unroll
            for (int nt = 0; nt < 4; ++nt) {
                ldsm_x2(bh[nt], aBh + nt * B_NT_BYTES + kt * KT_BYTES);
                ldsm_x2(bl[nt], aBl + nt * B_NT_BYTES + kt * KT_BYTES);
            }
#pragma unroll
            for (int mt = 0; mt < 4; ++mt)
#pragma unroll
                for (int nt = 0; nt < 4; ++nt)
                    mma_bf16(acc[mt][nt], ah[mt], bh[nt]);   // hi*hi
#pragma unroll
            for (int mt = 0; mt < 4; ++mt)
#pragma unroll
                for (int nt = 0; nt < 4; ++nt)
                    mma_bf16(acc[mt][nt], al[mt], bh[nt]);   // lo*hi
#pragma unroll
            for (int mt = 0; mt < 4; ++mt)
#pragma unroll
                for (int nt = 0; nt < 4; ++nt)
                    mma_bf16(acc[mt][nt], ah[mt], bl[nt]);   // hi*lo
        }

        // Epilogue: store 128x128 tile, both batch copies
#pragma unroll
        for (int mt = 0; mt < 4; ++mt) {
#pragma unroll
            for (int h = 0; h < 2; ++h) {
                int i = i0 + wm * 64 + mt * 16 + g + 8 * h;
                size_t rowoff = ((size_t)s * N_DIM + i) * N_DIM;
#pragma unroll
                for (int nt = 0; nt < 4; ++nt) {
                    int j = j0 + wn * 32 + nt * 8 + 2 * tg;
                    float2 v;
                    v.x = acc[mt][nt][2 * h + 0] + bv;
                    v.y = acc[mt][nt][2 * h + 1] + bv;
                    __stcs(reinterpret_cast<float2*>(&out[rowoff + j]), v);
                    __stcs(reinterpret_cast<float2*>(&out[rowoff + j + batch_stride]), v);
                }
            }
        }

        cur ^= 1;
    }
}

extern "C" void kernel_launch(void* const* d_in, const int* in_sizes, int n_in,
                              void* d_out, int out_size)
{
    const float* x0   = (const float*)d_in[0];  // tensor0 (S,N,D)
    const float* x1   = (const float*)d_in[1];  // tensor1 (S,N,D)
    const float* W    = (const float*)d_in[2];  // kernel  (D,D)
    const float* bias = (const float*)d_in[3];  // scalar
    float* out = (float*)d_out;                 // (2,S,N,N)

    cudaFuncSetAttribute(bilinear_mma_kernel,
                         cudaFuncAttributeMaxDynamicSharedMemorySize, SMEM_DYN);

    prep_kernel<<<256 + (S_DIM * N_DIM * D_DIM) / (256 * 4), 256>>>(x0, x1, W);

    bilinear_mma_kernel<<<NCTA, 256, SMEM_DYN>>>(bias, out);
}

// round 11
// speedup vs baseline: 1.4839x; 1.1957x over previous
#include <cuda_runtime.h>
#include <cuda_fp16.h>
#include <cstdint>

#define S_DIM 4
#define N_DIM 4096
#define D_DIM 64

// fp16 operand scratch, pair-packed along k: word = (h16 elem 2p | h16 elem 2p+1 << 16)
#define PAIR_WORDS (S_DIM * N_DIM * D_DIM / 2)
__device__ uint32_t g_Xf[PAIR_WORDS];   // x1 as fp16 pairs
__device__ uint32_t g_Qf[PAIR_WORDS];   // Q  as fp16 pairs

__device__ __forceinline__ uint32_t smem_u32(const void* p) {
    uint32_t a;
    asm("{ .reg .u64 t; cvta.to.shared.u64 t, %1; cvt.u32.u64 %0, t; }"
        : "=r"(a) : "l"(p));
    return a;
}
__device__ __forceinline__ uint32_t h2pack(float a, float b) {
    __half2 h = __floats2half2_rn(a, b);
    return *reinterpret_cast<uint32_t*>(&h);
}
// fp16 mma m16n8k16, fp32 accumulate (baseline PTX, valid on compute_103)
__device__ __forceinline__ void mma_fp16(float d[4], const uint32_t a[4], const uint32_t b[2]) {
    asm volatile(
        "mma.sync.aligned.m16n8k16.row.col.f32.f16.f16.f32 "
        "{%0,%1,%2,%3}, {%4,%5,%6,%7}, {%8,%9}, {%0,%1,%2,%3};"
        : "+f"(d[0]), "+f"(d[1]), "+f"(d[2]), "+f"(d[3])
        : "r"(a[0]), "r"(a[1]), "r"(a[2]), "r"(a[3]), "r"(b[0]), "r"(b[1]));
}
__device__ __forceinline__ void ldsm_x4(uint32_t r[4], uint32_t addr) {
    asm volatile("ldmatrix.sync.aligned.m8n8.x4.shared.b16 {%0,%1,%2,%3}, [%4];"
                 : "=r"(r[0]), "=r"(r[1]), "=r"(r[2]), "=r"(r[3]) : "r"(addr));
}
__device__ __forceinline__ void ldsm_x2(uint32_t r[2], uint32_t addr) {
    asm volatile("ldmatrix.sync.aligned.m8n8.x2.shared.b16 {%0,%1}, [%2];"
                 : "=r"(r[0]), "=r"(r[1]) : "r"(addr));
}

// ---------------------------------------------------------------------------
// Fused prep: blocks [0,256) compute Q (fp32 SIMT) -> fp16 pairs;
//             blocks [256,1280) convert x1 -> fp16 pairs.
// ---------------------------------------------------------------------------
__device__ __forceinline__ void load_tile_transposed64(
    const float* __restrict__ gsrc, float* sdst, int t)
{
    const float4* g4 = reinterpret_cast<const float4*>(gsrc);
#pragma unroll
    for (int p = 0; p < 4; ++p) {
        int f4 = p * 256 + t;
        int x  = f4 >> 4;
        int k4 = (f4 & 15) << 2;
        float4 v = g4[f4];
        float vv[4] = {v.x, v.y, v.z, v.w};
#pragma unroll
        for (int q = 0; q < 4; ++q) {
            int k  = k4 + q;
            int c4 = (x >> 2) ^ ((k >> 2) & 15);
            sdst[k * 64 + c4 * 4 + (x & 3)] = vv[q];
        }
    }
}

__global__ __launch_bounds__(256) void prep_kernel(
    const float* __restrict__ x0, const float* __restrict__ x1,
    const float* __restrict__ W)
{
    __shared__ float Xs[64 * 64];
    __shared__ float Ws[64 * 64];
    int t = threadIdx.x;

    if (blockIdx.x >= 256) {
        int i = (blockIdx.x - 256) * 256 + t;     // float4 index = uint2 pair index
        float4 v = reinterpret_cast<const float4*>(x1)[i];
        uint2 p;
        p.x = h2pack(v.x, v.y);
        p.y = h2pack(v.z, v.w);
        reinterpret_cast<uint2*>(g_Xf)[i] = p;
        return;
    }

    int r0 = blockIdx.x * 64;
    load_tile_transposed64(x0 + (size_t)r0 * 64, Xs, t);
    load_tile_transposed64(W, Ws, t);
    __syncthreads();

    int tx = t & 15, ty = t >> 4;
    float acc[4][4] = {};
#pragma unroll
    for (int k = 0; k < 64; ++k) {
        int sw = (k >> 2) & 15;
        float4 a = *reinterpret_cast<const float4*>(&Xs[k * 64 + ((ty ^ sw) << 2)]);
        float4 b = *reinterpret_cast<const float4*>(&Ws[k * 64 + ((tx ^ sw) << 2)]);
        float av[4] = {a.x, a.y, a.z, a.w};
        float bv[4] = {b.x, b.y, b.z, b.w};
#pragma unroll
        for (int ra = 0; ra < 4; ++ra)
#pragma unroll
            for (int rb = 0; rb < 4; ++rb)
                acc[ra][rb] += av[ra] * bv[rb];
    }

#pragma unroll
    for (int ra = 0; ra < 4; ++ra) {
        int r = r0 + ty * 4 + ra;
        uint2 p;
        p.x = h2pack(acc[ra][0], acc[ra][1]);
        p.y = h2pack(acc[ra][2], acc[ra][3]);
        *reinterpret_cast<uint2*>(&g_Qf[r * 32 + 2 * tx]) = p;
    }
}

// ---------------------------------------------------------------------------
// Stage 2: single-pass fp16 mma.sync GEMM (fp32 accumulate).
// CTA = 128x128 C tile, 256 threads = 8 warps (2m x 4n), warp = 64x32.
// kt-outer, full 4x4x4 accumulator, ldmatrix fragments.
// Smem: 2 tiles [128 rows][36 pair-words] = 36.9 KB -> 2 CTAs/SM.
// ---------------------------------------------------------------------------
#define PADW 36
#define TILE_W (128 * PADW)
#define SMEM_DYN (2 * TILE_W * 4)
#define A_MT_BYTES (16 * PADW * 4)      // 16 rows
#define B_NT_BYTES (8 * PADW * 4)       // 8 rows
#define KT_BYTES   32                   // 8 pair-words = 16 fp16

__device__ __forceinline__ void fill_tile_async(
    const uint32_t* __restrict__ gsrc, uint32_t* sdst, int t)
{
#pragma unroll
    for (int it = 0; it < 4; ++it) {
        int f4 = it * 256 + t;          // 0..1023 16B chunks (128 rows x 8)
        int r  = f4 >> 3;
        int c4 = f4 & 7;
        uint32_t sa = smem_u32(&sdst[r * PADW + c4 * 4]);
        asm volatile("cp.async.cg.shared.global [%0], [%1], 16;"
                     :: "r"(sa), "l"(gsrc + f4 * 4) : "memory");
    }
}

__global__ __launch_bounds__(256, 2) void bilinear_mma_kernel(
    const float* __restrict__ bias, float* __restrict__ out)
{
    extern __shared__ uint32_t sm[];
    uint32_t* Af = sm;
    uint32_t* Bf = sm + TILE_W;

    int t    = threadIdx.x;
    int warp = t >> 5;
    int lane = t & 31;
    int wm   = warp >> 2;      // 0..1  (m, 64 rows)
    int wn   = warp & 3;       // 0..3  (n, 32 cols)
    int g    = lane >> 2;      // 0..7
    int tg   = lane & 3;       // 0..3

    int s  = blockIdx.z;
    int i0 = blockIdx.y * 128;
    int j0 = blockIdx.x * 128;

    size_t abase = (size_t)(s * N_DIM + i0) * (D_DIM / 2);
    size_t bbase = (size_t)(s * N_DIM + j0) * (D_DIM / 2);
    fill_tile_async(g_Xf + abase, Af, t);
    fill_tile_async(g_Qf + bbase, Bf, t);
    asm volatile("cp.async.commit_group;" ::: "memory");
    asm volatile("cp.async.wait_group 0;" ::: "memory");
    __syncthreads();

    // ldmatrix per-lane row addressing (same geometry as round 8; b16 elements)
    int rowA   = (lane & 7) + 8 * ((lane >> 3) & 1);
    int kplusA = (lane >> 4) & 1;
    int rowB   = lane & 7;
    int kplusB = (lane >> 3) & 1;

    uint32_t aAf = smem_u32(Af) + ((wm * 64 + rowA) * PADW + kplusA * 4) * 4;
    uint32_t aBf = smem_u32(Bf) + ((wn * 32 + rowB) * PADW + kplusB * 4) * 4;

    float acc[4][4][4];
#pragma unroll
    for (int a = 0; a < 4; ++a)
#pragma unroll
        for (int b = 0; b < 4; ++b)
#pragma unroll
            for (int c = 0; c < 4; ++c) acc[a][b][c] = 0.0f;

#pragma unroll
    for (int kt = 0; kt < 4; ++kt) {
        uint32_t af[4][4];              // [mt][reg]
        uint32_t bf[4][2];              // [nt][reg]
#pragma unroll
        for (int mt = 0; mt < 4; ++mt)
            ldsm_x4(af[mt], aAf + mt * A_MT_BYTES + kt * KT_BYTES);
#pragma unroll
        for (int nt = 0; nt < 4; ++nt)
            ldsm_x2(bf[nt], aBf + nt * B_NT_BYTES + kt * KT_BYTES);

#pragma unroll
        for (int mt = 0; mt < 4; ++mt)
#pragma unroll
            for (int nt = 0; nt < 4; ++nt)
                mma_fp16(acc[mt][nt], af[mt], bf[nt]);
    }

    float bv = __ldg(bias);
    const size_t batch_stride = (size_t)S_DIM * N_DIM * N_DIM;

    // Epilogue: c0,c1 -> (row g, cols 2tg,2tg+1); c2,c3 -> row g+8
#pragma unroll
    for (int mt = 0; mt < 4; ++mt) {
#pragma unroll
        for (int h = 0; h < 2; ++h) {
            int i = i0 + wm * 64 + mt * 16 + g + 8 * h;
            size_t rowoff = ((size_t)s * N_DIM + i) * N_DIM;
#pragma unroll
            for (int nt = 0; nt < 4; ++nt) {
                int j = j0 + wn * 32 + nt * 8 + 2 * tg;
                float2 v;
                v.x = acc[mt][nt][2 * h + 0] + bv;
                v.y = acc[mt][nt][2 * h + 1] + bv;
                __stcs(reinterpret_cast<float2*>(&out[rowoff + j]), v);
                __stcs(reinterpret_cast<float2*>(&out[rowoff + j + batch_stride]), v);
            }
        }
    }
}

extern "C" void kernel_launch(void* const* d_in, const int* in_sizes, int n_in,
                              void* d_out, int out_size)
{
    const float* x0   = (const float*)d_in[0];  // tensor0 (S,N,D)
    const float* x1   = (const float*)d_in[1];  // tensor1 (S,N,D)
    const float* W    = (const float*)d_in[2];  // kernel  (D,D)
    const float* bias = (const float*)d_in[3];  // scalar
    float* out = (float*)d_out;                 // (2,S,N,N)

    cudaFuncSetAttribute(bilinear_mma_kernel,
                         cudaFuncAttributeMaxDynamicSharedMemorySize, SMEM_DYN);

    prep_kernel<<<256 + (S_DIM * N_DIM * D_DIM) / (256 * 4), 256>>>(x0, x1, W);

    dim3 grid(N_DIM / 128, N_DIM / 128, S_DIM);
    bilinear_mma_kernel<<<grid, 256, SMEM_DYN>>>(bias, out);
}

// round 12
// speedup vs baseline: 1.5247x; 1.0275x over previous
#include <cuda_runtime.h>
#include <cuda_fp16.h>
#include <cstdint>

#define S_DIM 4
#define N_DIM 4096
#define D_DIM 64

// fp16 operand scratch, pair-packed along k: word = (h16 elem 2p | h16 elem 2p+1 << 16)
#define PAIR_WORDS (S_DIM * N_DIM * D_DIM / 2)
__device__ uint32_t g_Xf[PAIR_WORDS];   // x1 as fp16 pairs
__device__ uint32_t g_Qf[PAIR_WORDS];   // Q  as fp16 pairs

__device__ __forceinline__ uint32_t smem_u32(const void* p) {
    uint32_t a;
    asm("{ .reg .u64 t; cvta.to.shared.u64 t, %1; cvt.u32.u64 %0, t; }"
        : "=r"(a) : "l"(p));
    return a;
}
__device__ __forceinline__ uint32_t h2pack(float a, float b) {
    __half2 h = __floats2half2_rn(a, b);
    return *reinterpret_cast<uint32_t*>(&h);
}
// fp16 mma m16n8k16, fp32 accumulate (baseline PTX, valid on compute_103)
__device__ __forceinline__ void mma_fp16(float d[4], const uint32_t a[4], const uint32_t b[2]) {
    asm volatile(
        "mma.sync.aligned.m16n8k16.row.col.f32.f16.f16.f32 "
        "{%0,%1,%2,%3}, {%4,%5,%6,%7}, {%8,%9}, {%0,%1,%2,%3};"
        : "+f"(d[0]), "+f"(d[1]), "+f"(d[2]), "+f"(d[3])
        : "r"(a[0]), "r"(a[1]), "r"(a[2]), "r"(a[3]), "r"(b[0]), "r"(b[1]));
}
__device__ __forceinline__ void ldsm_x4(uint32_t r[4], uint32_t addr) {
    asm volatile("ldmatrix.sync.aligned.m8n8.x4.shared.b16 {%0,%1,%2,%3}, [%4];"
                 : "=r"(r[0]), "=r"(r[1]), "=r"(r[2]), "=r"(r[3]) : "r"(addr));
}
__device__ __forceinline__ void ldsm_x2(uint32_t r[2], uint32_t addr) {
    asm volatile("ldmatrix.sync.aligned.m8n8.x2.shared.b16 {%0,%1}, [%2];"
                 : "=r"(r[0]), "=r"(r[1]) : "r"(addr));
}

// ---------------------------------------------------------------------------
// Fused prep: blocks [0,256) compute Q (fp32 SIMT) -> fp16 pairs;
//             blocks [256,1280) convert x1 -> fp16 pairs.
// ---------------------------------------------------------------------------
__device__ __forceinline__ void load_tile_transposed64(
    const float* __restrict__ gsrc, float* sdst, int t)
{
    const float4* g4 = reinterpret_cast<const float4*>(gsrc);
#pragma unroll
    for (int p = 0; p < 4; ++p) {
        int f4 = p * 256 + t;
        int x  = f4 >> 4;
        int k4 = (f4 & 15) << 2;
        float4 v = g4[f4];
        float vv[4] = {v.x, v.y, v.z, v.w};
#pragma unroll
        for (int q = 0; q < 4; ++q) {
            int k  = k4 + q;
            int c4 = (x >> 2) ^ ((k >> 2) & 15);
            sdst[k * 64 + c4 * 4 + (x & 3)] = vv[q];
        }
    }
}

__global__ __launch_bounds__(256) void prep_kernel(
    const float* __restrict__ x0, const float* __restrict__ x1,
    const float* __restrict__ W)
{
    __shared__ float Xs[64 * 64];
    __shared__ float Ws[64 * 64];
    int t = threadIdx.x;

    if (blockIdx.x >= 256) {
        int i = (blockIdx.x - 256) * 256 + t;     // float4 index = uint2 pair index
        float4 v = reinterpret_cast<const float4*>(x1)[i];
        uint2 p;
        p.x = h2pack(v.x, v.y);
        p.y = h2pack(v.z, v.w);
        reinterpret_cast<uint2*>(g_Xf)[i] = p;
        return;
    }

    int r0 = blockIdx.x * 64;
    load_tile_transposed64(x0 + (size_t)r0 * 64, Xs, t);
    load_tile_transposed64(W, Ws, t);
    __syncthreads();

    int tx = t & 15, ty = t >> 4;
    float acc[4][4] = {};
#pragma unroll
    for (int k = 0; k < 64; ++k) {
        int sw = (k >> 2) & 15;
        float4 a = *reinterpret_cast<const float4*>(&Xs[k * 64 + ((ty ^ sw) << 2)]);
        float4 b = *reinterpret_cast<const float4*>(&Ws[k * 64 + ((tx ^ sw) << 2)]);
        float av[4] = {a.x, a.y, a.z, a.w};
        float bv[4] = {b.x, b.y, b.z, b.w};
#pragma unroll
        for (int ra = 0; ra < 4; ++ra)
#pragma unroll
            for (int rb = 0; rb < 4; ++rb)
                acc[ra][rb] += av[ra] * bv[rb];
    }

#pragma unroll
    for (int ra = 0; ra < 4; ++ra) {
        int r = r0 + ty * 4 + ra;
        uint2 p;
        p.x = h2pack(acc[ra][0], acc[ra][1]);
        p.y = h2pack(acc[ra][2], acc[ra][3]);
        *reinterpret_cast<uint2*>(&g_Qf[r * 32 + 2 * tx]) = p;
    }
}

// ---------------------------------------------------------------------------
// Stage 2: single-pass fp16 mma.sync GEMM (fp32 accumulate) with
// smem-staged fully-coalesced epilogue.
// CTA = 128x128 C tile, 256 threads = 8 warps (2m x 4n), warp = 64x32.
// Smem: 2 operand tiles [128][36 pair-words] (36.9 KB) + stage 64x136 fp32
// (34 KB) = 70 KB -> 2 CTAs/SM.
// ---------------------------------------------------------------------------
#define PADW 36
#define TILE_W (128 * PADW)
#define STG_STRIDE 136                  // floats per staged row (bank-safe)
#define STAGE_FLOATS (64 * STG_STRIDE)
#define SMEM_DYN (2 * TILE_W * 4 + STAGE_FLOATS * 4)
#define A_MT_BYTES (16 * PADW * 4)      // 16 rows
#define B_NT_BYTES (8 * PADW * 4)       // 8 rows
#define KT_BYTES   32                   // 8 pair-words = 16 fp16

__device__ __forceinline__ void fill_tile_async(
    const uint32_t* __restrict__ gsrc, uint32_t* sdst, int t)
{
#pragma unroll
    for (int it = 0; it < 4; ++it) {
        int f4 = it * 256 + t;          // 0..1023 16B chunks (128 rows x 8)
        int r  = f4 >> 3;
        int c4 = f4 & 7;
        uint32_t sa = smem_u32(&sdst[r * PADW + c4 * 4]);
        asm volatile("cp.async.cg.shared.global [%0], [%1], 16;"
                     :: "r"(sa), "l"(gsrc + f4 * 4) : "memory");
    }
}

__global__ __launch_bounds__(256, 2) void bilinear_mma_kernel(
    const float* __restrict__ bias, float* __restrict__ out)
{
    extern __shared__ uint32_t sm[];
    uint32_t* Af = sm;
    uint32_t* Bf = sm + TILE_W;
    float* stage = reinterpret_cast<float*>(sm + 2 * TILE_W);

    int t    = threadIdx.x;
    int warp = t >> 5;
    int lane = t & 31;
    int wm   = warp >> 2;      // 0..1  (m, 64 rows)
    int wn   = warp & 3;       // 0..3  (n, 32 cols)
    int g    = lane >> 2;      // 0..7
    int tg   = lane & 3;       // 0..3

    int s  = blockIdx.z;
    int i0 = blockIdx.y * 128;
    int j0 = blockIdx.x * 128;

    size_t abase = (size_t)(s * N_DIM + i0) * (D_DIM / 2);
    size_t bbase = (size_t)(s * N_DIM + j0) * (D_DIM / 2);
    fill_tile_async(g_Xf + abase, Af, t);
    fill_tile_async(g_Qf + bbase, Bf, t);
    asm volatile("cp.async.commit_group;" ::: "memory");
    asm volatile("cp.async.wait_group 0;" ::: "memory");
    __syncthreads();

    // ldmatrix per-lane row addressing (b16 elements)
    int rowA   = (lane & 7) + 8 * ((lane >> 3) & 1);
    int kplusA = (lane >> 4) & 1;
    int rowB   = lane & 7;
    int kplusB = (lane >> 3) & 1;

    uint32_t aAf = smem_u32(Af) + ((wm * 64 + rowA) * PADW + kplusA * 4) * 4;
    uint32_t aBf = smem_u32(Bf) + ((wn * 32 + rowB) * PADW + kplusB * 4) * 4;

    float acc[4][4][4];
#pragma unroll
    for (int a = 0; a < 4; ++a)
#pragma unroll
        for (int b = 0; b < 4; ++b)
#pragma unroll
            for (int c = 0; c < 4; ++c) acc[a][b][c] = 0.0f;

#pragma unroll
    for (int kt = 0; kt < 4; ++kt) {
        uint32_t af[4][4];              // [mt][reg]
        uint32_t bf[4][2];              // [nt][reg]
#pragma unroll
        for (int mt = 0; mt < 4; ++mt)
            ldsm_x4(af[mt], aAf + mt * A_MT_BYTES + kt * KT_BYTES);
#pragma unroll
        for (int nt = 0; nt < 4; ++nt)
            ldsm_x2(bf[nt], aBf + nt * B_NT_BYTES + kt * KT_BYTES);

#pragma unroll
        for (int mt = 0; mt < 4; ++mt)
#pragma unroll
            for (int nt = 0; nt < 4; ++nt)
                mma_fp16(acc[mt][nt], af[mt], bf[nt]);
    }

    float bv = __ldg(bias);
    const size_t batch_stride = (size_t)S_DIM * N_DIM * N_DIM;

    // Staged epilogue, two 64-row halves.
    // half hf covers tile rows {wm*64 + (2hf+m)*16 + g + 8h}; staged at
    // L = wm*32 + m*16 + g + 8h (0..63). Reader inverts the map.
#pragma unroll
    for (int hf = 0; hf < 2; ++hf) {
        __syncthreads();
        // STS accs (+bias); banks (8g+2tg) per phase: conflict-free
#pragma unroll
        for (int m = 0; m < 2; ++m) {
            int mt = 2 * hf + m;
#pragma unroll
            for (int h = 0; h < 2; ++h) {
                int L = wm * 32 + m * 16 + g + 8 * h;
#pragma unroll
                for (int nt = 0; nt < 4; ++nt) {
                    float2 v;
                    v.x = acc[mt][nt][2 * h + 0] + bv;
                    v.y = acc[mt][nt][2 * h + 1] + bv;
                    *reinterpret_cast<float2*>(
                        &stage[L * STG_STRIDE + wn * 32 + nt * 8 + 2 * tg]) = v;
                }
            }
        }
        __syncthreads();
        // Coalesced store: warp reads full 128-float rows, STG.128 x 512B runs
#pragma unroll
        for (int rr = 0; rr < 8; ++rr) {
            int L = warp + rr * 8;      // 0..63
            int irel = ((L >> 5) << 6) + ((2 * hf + ((L >> 4) & 1)) << 4) + (L & 15);
            size_t rowoff = ((size_t)s * N_DIM + i0 + irel) * N_DIM + j0;
            float4 v = *reinterpret_cast<float4*>(&stage[L * STG_STRIDE + lane * 4]);
            __stcs(reinterpret_cast<float4*>(&out[rowoff + lane * 4]), v);
            __stcs(reinterpret_cast<float4*>(&out[rowoff + lane * 4 + batch_stride]), v);
        }
    }
}

extern "C" void kernel_launch(void* const* d_in, const int* in_sizes, int n_in,
                              void* d_out, int out_size)
{
    const float* x0   = (const float*)d_in[0];  // tensor0 (S,N,D)
    const float* x1   = (const float*)d_in[1];  // tensor1 (S,N,D)
    const float* W    = (const float*)d_in[2];  // kernel  (D,D)
    const float* bias = (const float*)d_in[3];  // scalar
    float* out = (float*)d_out;                 // (2,S,N,N)

    cudaFuncSetAttribute(bilinear_mma_kernel,
                         cudaFuncAttributeMaxDynamicSharedMemorySize, SMEM_DYN);

    prep_kernel<<<256 + (S_DIM * N_DIM * D_DIM) / (256 * 4), 256>>>(x0, x1, W);

    dim3 grid(N_DIM / 128, N_DIM / 128, S_DIM);
    bilinear_mma_kernel<<<grid, 256, SMEM_DYN>>>(bias, out);
}

// round 13
// speedup vs baseline: 1.6466x; 1.0799x over previous
#include <cuda_runtime.h>
#include <cuda_fp16.h>
#include <cstdint>

#define S_DIM 4
#define N_DIM 4096
#define D_DIM 64

// fp16 operand scratch, pair-packed along k: word = (h16 elem 2p | h16 elem 2p+1 << 16)
#define PAIR_WORDS (S_DIM * N_DIM * D_DIM / 2)
__device__ uint32_t g_Xf[PAIR_WORDS];   // x1 as fp16 pairs
__device__ uint32_t g_Qf[PAIR_WORDS];   // Q  as fp16 pairs

__device__ __forceinline__ uint32_t smem_u32(const void* p) {
    uint32_t a;
    asm("{ .reg .u64 t; cvta.to.shared.u64 t, %1; cvt.u32.u64 %0, t; }"
        : "=r"(a) : "l"(p));
    return a;
}
__device__ __forceinline__ uint32_t h2pack(float a, float b) {
    __half2 h = __floats2half2_rn(a, b);
    return *reinterpret_cast<uint32_t*>(&h);
}
// fp16 mma m16n8k16, fp32 accumulate (baseline PTX, valid on compute_103)
__device__ __forceinline__ void mma_fp16(float d[4], const uint32_t a[4], const uint32_t b[2]) {
    asm volatile(
        "mma.sync.aligned.m16n8k16.row.col.f32.f16.f16.f32 "
        "{%0,%1,%2,%3}, {%4,%5,%6,%7}, {%8,%9}, {%0,%1,%2,%3};"
        : "+f"(d[0]), "+f"(d[1]), "+f"(d[2]), "+f"(d[3])
        : "r"(a[0]), "r"(a[1]), "r"(a[2]), "r"(a[3]), "r"(b[0]), "r"(b[1]));
}
__device__ __forceinline__ void ldsm_x4(uint32_t r[4], uint32_t addr) {
    asm volatile("ldmatrix.sync.aligned.m8n8.x4.shared.b16 {%0,%1,%2,%3}, [%4];"
                 : "=r"(r[0]), "=r"(r[1]), "=r"(r[2]), "=r"(r[3]) : "r"(addr));
}
__device__ __forceinline__ void ldsm_x2(uint32_t r[2], uint32_t addr) {
    asm volatile("ldmatrix.sync.aligned.m8n8.x2.shared.b16 {%0,%1}, [%2];"
                 : "=r"(r[0]), "=r"(r[1]) : "r"(addr));
}

// ---------------------------------------------------------------------------
// Fused prep: blocks [0,256) compute Q (fp32 SIMT) -> fp16 pairs;
//             blocks [256,1280) convert x1 -> fp16 pairs.
// ---------------------------------------------------------------------------
__device__ __forceinline__ void load_tile_transposed64(
    const float* __restrict__ gsrc, float* sdst, int t)
{
    const float4* g4 = reinterpret_cast<const float4*>(gsrc);
#pragma unroll
    for (int p = 0; p < 4; ++p) {
        int f4 = p * 256 + t;
        int x  = f4 >> 4;
        int k4 = (f4 & 15) << 2;
        float4 v = g4[f4];
        float vv[4] = {v.x, v.y, v.z, v.w};
#pragma unroll
        for (int q = 0; q < 4; ++q) {
            int k  = k4 + q;
            int c4 = (x >> 2) ^ ((k >> 2) & 15);
            sdst[k * 64 + c4 * 4 + (x & 3)] = vv[q];
        }
    }
}

__global__ __launch_bounds__(256) void prep_kernel(
    const float* __restrict__ x0, const float* __restrict__ x1,
    const float* __restrict__ W)
{
    __shared__ float Xs[64 * 64];
    __shared__ float Ws[64 * 64];
    int t = threadIdx.x;

    if (blockIdx.x >= 256) {
        int i = (blockIdx.x - 256) * 256 + t;     // float4 index = uint2 pair index
        float4 v = reinterpret_cast<const float4*>(x1)[i];
        uint2 p;
        p.x = h2pack(v.x, v.y);
        p.y = h2pack(v.z, v.w);
        reinterpret_cast<uint2*>(g_Xf)[i] = p;
        return;
    }

    int r0 = blockIdx.x * 64;
    load_tile_transposed64(x0 + (size_t)r0 * 64, Xs, t);
    load_tile_transposed64(W, Ws, t);
    __syncthreads();

    int tx = t & 15, ty = t >> 4;
    float acc[4][4] = {};
#pragma unroll
    for (int k = 0; k < 64; ++k) {
        int sw = (k >> 2) & 15;
        float4 a = *reinterpret_cast<const float4*>(&Xs[k * 64 + ((ty ^ sw) << 2)]);
        float4 b = *reinterpret_cast<const float4*>(&Ws[k * 64 + ((tx ^ sw) << 2)]);
        float av[4] = {a.x, a.y, a.z, a.w};
        float bv[4] = {b.x, b.y, b.z, b.w};
#pragma unroll
        for (int ra = 0; ra < 4; ++ra)
#pragma unroll
            for (int rb = 0; rb < 4; ++rb)
                acc[ra][rb] += av[ra] * bv[rb];
    }

#pragma unroll
    for (int ra = 0; ra < 4; ++ra) {
        int r = r0 + ty * 4 + ra;
        uint2 p;
        p.x = h2pack(acc[ra][0], acc[ra][1]);
        p.y = h2pack(acc[ra][2], acc[ra][3]);
        *reinterpret_cast<uint2*>(&g_Qf[r * 32 + 2 * tx]) = p;
    }
}

// ---------------------------------------------------------------------------
// Stage 2: single-pass fp16 mma.sync GEMM, half-outer structure.
// CTA = 128x128 C tile, 256 threads = 8 warps (2m x 4n), warp = 64x32.
// Two halves (mt 0-1 rows 0..63 of warp band, mt 2-3 rows 64..127 interleaved
// per wm): compute half -> staged coalesced store half, so the second half's
// MMA overlaps the first half's store drain. 32-reg accumulator -> 3 CTAs/SM.
// Smem: 2 operand tiles [128][36 pair-words] (36.9 KB) + stage 64x136 fp32
// (34 KB) = 70.9 KB; x3 CTAs = 213 KB.
// ---------------------------------------------------------------------------
#define PADW 36
#define TILE_W (128 * PADW)
#define STG_STRIDE 136                  // floats per staged row (bank-safe)
#define STAGE_FLOATS (64 * STG_STRIDE)
#define SMEM_DYN (2 * TILE_W * 4 + STAGE_FLOATS * 4)
#define A_MT_BYTES (16 * PADW * 4)      // 16 rows
#define B_NT_BYTES (8 * PADW * 4)       // 8 rows
#define KT_BYTES   32                   // 8 pair-words = 16 fp16

__device__ __forceinline__ void fill_tile_async(
    const uint32_t* __restrict__ gsrc, uint32_t* sdst, int t)
{
#pragma unroll
    for (int it = 0; it < 4; ++it) {
        int f4 = it * 256 + t;          // 0..1023 16B chunks (128 rows x 8)
        int r  = f4 >> 3;
        int c4 = f4 & 7;
        uint32_t sa = smem_u32(&sdst[r * PADW + c4 * 4]);
        asm volatile("cp.async.cg.shared.global [%0], [%1], 16;"
                     :: "r"(sa), "l"(gsrc + f4 * 4) : "memory");
    }
}

__global__ __launch_bounds__(256, 3) void bilinear_mma_kernel(
    const float* __restrict__ bias, float* __restrict__ out)
{
    extern __shared__ uint32_t sm[];
    uint32_t* Af = sm;
    uint32_t* Bf = sm + TILE_W;
    float* stage = reinterpret_cast<float*>(sm + 2 * TILE_W);

    int t    = threadIdx.x;
    int warp = t >> 5;
    int lane = t & 31;
    int wm   = warp >> 2;      // 0..1  (m, 64 rows)
    int wn   = warp & 3;       // 0..3  (n, 32 cols)
    int g    = lane >> 2;      // 0..7
    int tg   = lane & 3;       // 0..3

    int s  = blockIdx.z;
    int i0 = blockIdx.y * 128;
    int j0 = blockIdx.x * 128;

    size_t abase = (size_t)(s * N_DIM + i0) * (D_DIM / 2);
    size_t bbase = (size_t)(s * N_DIM + j0) * (D_DIM / 2);
    fill_tile_async(g_Xf + abase, Af, t);
    fill_tile_async(g_Qf + bbase, Bf, t);
    asm volatile("cp.async.commit_group;" ::: "memory");
    asm volatile("cp.async.wait_group 0;" ::: "memory");
    __syncthreads();

    // ldmatrix per-lane row addressing (b16 elements)
    int rowA   = (lane & 7) + 8 * ((lane >> 3) & 1);
    int kplusA = (lane >> 4) & 1;
    int rowB   = lane & 7;
    int kplusB = (lane >> 3) & 1;

    uint32_t aAf = smem_u32(Af) + ((wm * 64 + rowA) * PADW + kplusA * 4) * 4;
    uint32_t aBf = smem_u32(Bf) + ((wn * 32 + rowB) * PADW + kplusB * 4) * 4;

    float bv = __ldg(bias);
    const size_t batch_stride = (size_t)S_DIM * N_DIM * N_DIM;

#pragma unroll
    for (int hf = 0; hf < 2; ++hf) {
        // ---- compute half: mt = 2hf, 2hf+1 ----
        float acc[2][4][4];
#pragma unroll
        for (int a = 0; a < 2; ++a)
#pragma unroll
            for (int b = 0; b < 4; ++b)
#pragma unroll
                for (int c = 0; c < 4; ++c) acc[a][b][c] = 0.0f;

#pragma unroll
        for (int kt = 0; kt < 4; ++kt) {
            uint32_t af[2][4];
            uint32_t bf[4][2];
#pragma unroll
            for (int m = 0; m < 2; ++m)
                ldsm_x4(af[m], aAf + (2 * hf + m) * A_MT_BYTES + kt * KT_BYTES);
#pragma unroll
            for (int nt = 0; nt < 4; ++nt)
                ldsm_x2(bf[nt], aBf + nt * B_NT_BYTES + kt * KT_BYTES);

#pragma unroll
            for (int m = 0; m < 2; ++m)
#pragma unroll
                for (int nt = 0; nt < 4; ++nt)
                    mma_fp16(acc[m][nt], af[m], bf[nt]);
        }

        // ---- store half via stage ----
        __syncthreads();   // stage free (prev half's readers done)
#pragma unroll
        for (int m = 0; m < 2; ++m) {
#pragma unroll
            for (int h = 0; h < 2; ++h) {
                int L = wm * 32 + m * 16 + g + 8 * h;
#pragma unroll
                for (int nt = 0; nt < 4; ++nt) {
                    float2 v;
                    v.x = acc[m][nt][2 * h + 0] + bv;
                    v.y = acc[m][nt][2 * h + 1] + bv;
                    *reinterpret_cast<float2*>(
                        &stage[L * STG_STRIDE + wn * 32 + nt * 8 + 2 * tg]) = v;
                }
            }
        }
        __syncthreads();
        // Coalesced: warp reads full 128-float rows, 512B STG.128 runs
#pragma unroll
        for (int rr = 0; rr < 8; ++rr) {
            int L = warp + rr * 8;      // 0..63
            int irel = ((L >> 5) << 6) + ((2 * hf + ((L >> 4) & 1)) << 4) + (L & 15);
            size_t rowoff = ((size_t)s * N_DIM + i0 + irel) * N_DIM + j0;
            float4 v = *reinterpret_cast<float4*>(&stage[L * STG_STRIDE + lane * 4]);
            __stcs(reinterpret_cast<float4*>(&out[rowoff + lane * 4]), v);
            __stcs(reinterpret_cast<float4*>(&out[rowoff + lane * 4 + batch_stride]), v);
        }
    }
}

extern "C" void kernel_launch(void* const* d_in, const int* in_sizes, int n_in,
                              void* d_out, int out_size)
{
    const float* x0   = (const float*)d_in[0];  // tensor0 (S,N,D)
    const float* x1   = (const float*)d_in[1];  // tensor1 (S,N,D)
    const float* W    = (const float*)d_in[2];  // kernel  (D,D)
    const float* bias = (const float*)d_in[3];  // scalar
    float* out = (float*)d_out;                 // (2,S,N,N)

    cudaFuncSetAttribute(bilinear_mma_kernel,
                         cudaFuncAttributeMaxDynamicSharedMemorySize, SMEM_DYN);

    prep_kernel<<<256 + (S_DIM * N_DIM * D_DIM) / (256 * 4), 256>>>(x0, x1, W);

    dim3 grid(N_DIM / 128, N_DIM / 128, S_DIM);
    bilinear_mma_kernel<<<grid, 256, SMEM_DYN>>>(bias, out);
}